// round 15
// baseline (speedup 1.0000x reference)
#include <cuda_runtime.h>

// ---------------------------------------------------------------------------
// MatchingLayer: B=8, S=2048, H=1024
//   scores  = (X @ X^T) / sqrt(H)                      [B,S,S]
//   probs   = softmax(scores*mask - 1e9*(1-mask))      [B,S,S]
//   context = probs @ X                                 [B,S,H]
//   match   = [X | context] @ W(2H,H) + b               [B,S,H]
//   out     = LayerNorm(match) * gamma + beta           [B,S,H]
// ---------------------------------------------------------------------------

namespace {
constexpr int B_ = 8;
constexpr int S_ = 2048;
constexpr int H_ = 1024;
constexpr int BM = 128, BN = 128, BK = 16;
constexpr float SCALE = 0.03125f;      // 1/sqrt(1024)
constexpr float MASKC = 1.0e9f;        // MASK_LOGIT_CONST
constexpr float LN_EPS = 1e-12f;
}

// Scratch (module-static device memory; no runtime allocation).
__device__ __align__(16) float g_probs[(size_t)B_ * S_ * S_];   // 134 MB, reused scores->probs
__device__ __align__(16) float g_ctx  [(size_t)B_ * S_ * H_];   // 67 MB
__device__ __align__(16) float g_match[(size_t)B_ * S_ * H_];   // 67 MB

// ---------------------------------------------------------------------------
// Tiled SGEMM, 128x128x16 tile, 256 threads, 8x8 register microtile.
// MODE 0: C = Xb @ Xb^T * SCALE        (M=S, N=S, K=H)   -> g_probs
// MODE 1: C = Pb @ Xb                  (M=S, N=H, K=S)   -> g_ctx
// MODE 2: C = [Xb|Ctx] @ W + bias      (M=S, N=H, K=2H)  -> g_match
// ---------------------------------------------------------------------------
template <int MODE>
__global__ __launch_bounds__(256, 2)
void k_gemm(const float* __restrict__ X,
            const float* __restrict__ W,
            const float* __restrict__ bias) {
    constexpr int KDIM = (MODE == 0) ? H_ : (MODE == 1 ? S_ : 2 * H_);
    const int b  = blockIdx.z;
    const int bm = blockIdx.y * BM;
    const int bn = blockIdx.x * BN;

    const float* Xb  = X + (size_t)b * S_ * H_;
    const float* Pb  = g_probs + (size_t)b * S_ * S_;
    const float* Ctx = g_ctx   + (size_t)b * S_ * H_;
    float* C = (MODE == 0) ? g_probs + (size_t)b * S_ * S_
             : (MODE == 1) ? g_ctx   + (size_t)b * S_ * H_
                           : g_match + (size_t)b * S_ * H_;
    const int ldc = (MODE == 0) ? S_ : H_;

    __shared__ __align__(16) float As[BK][BM + 4];
    __shared__ __align__(16) float Bs[BK][BN + 4];

    const int tid  = threadIdx.x;
    const int lrow = tid >> 2;           // 0..63 (transposed-loader row)
    const int lk   = (tid & 3) * 4;      // 0,4,8,12
    const int brow = tid >> 5;           // 0..7  (direct B loader row)
    const int bcol = (tid & 31) * 4;     // 0..124
    const int tx = tid & 15, ty = tid >> 4;
    const int m0 = ty * 8, n0 = tx * 8;

    float acc[8][8];
#pragma unroll
    for (int i = 0; i < 8; i++)
#pragma unroll
        for (int j = 0; j < 8; j++) acc[i][j] = 0.0f;

    // A is always loaded "transposed" (As[k][m]) from a row-major [M,K] source.
    auto loadA = [&](int row, int k0) -> float4 {
        if (MODE == 0)
            return *(const float4*)(Xb + (size_t)(bm + row) * H_ + k0 + lk);
        else if (MODE == 1)
            return *(const float4*)(Pb + (size_t)(bm + row) * S_ + k0 + lk);
        else {
            int kk = k0 + lk;   // whole BK-tile is on one side of H (H % BK == 0)
            const float* src = (kk < H_)
                ? (Xb  + (size_t)(bm + row) * H_ + kk)
                : (Ctx + (size_t)(bm + row) * H_ + (kk - H_));
            return *(const float4*)src;
        }
    };
    // MODE 0: B tile is also transposed rows of Xb (for X @ X^T).
    auto loadBtr = [&](int row, int k0) -> float4 {
        return *(const float4*)(Xb + (size_t)(bn + row) * H_ + k0 + lk);
    };
    // MODE 1/2: B is row-major [K,N]; direct load Bs[k][n].
    auto loadBdir = [&](int r, int k0) -> float4 {
        const float* base = (MODE == 1) ? Xb : W;
        return *(const float4*)(base + (size_t)(k0 + r) * H_ + bn + bcol);
    };

    float4 pa0 = loadA(lrow, 0);
    float4 pa1 = loadA(lrow + 64, 0);
    float4 pb0, pb1;
    if (MODE == 0) { pb0 = loadBtr(lrow, 0);  pb1 = loadBtr(lrow + 64, 0); }
    else           { pb0 = loadBdir(brow, 0); pb1 = loadBdir(brow + 8, 0); }

    for (int k0 = 0; k0 < KDIM; k0 += BK) {
        // commit prefetched tile to smem
        As[lk + 0][lrow] = pa0.x; As[lk + 1][lrow] = pa0.y;
        As[lk + 2][lrow] = pa0.z; As[lk + 3][lrow] = pa0.w;
        As[lk + 0][lrow + 64] = pa1.x; As[lk + 1][lrow + 64] = pa1.y;
        As[lk + 2][lrow + 64] = pa1.z; As[lk + 3][lrow + 64] = pa1.w;
        if (MODE == 0) {
            Bs[lk + 0][lrow] = pb0.x; Bs[lk + 1][lrow] = pb0.y;
            Bs[lk + 2][lrow] = pb0.z; Bs[lk + 3][lrow] = pb0.w;
            Bs[lk + 0][lrow + 64] = pb1.x; Bs[lk + 1][lrow + 64] = pb1.y;
            Bs[lk + 2][lrow + 64] = pb1.z; Bs[lk + 3][lrow + 64] = pb1.w;
        } else {
            *(float4*)&Bs[brow][bcol]     = pb0;
            *(float4*)&Bs[brow + 8][bcol] = pb1;
        }
        __syncthreads();

        const int kn = k0 + BK;
        if (kn < KDIM) {  // prefetch next tile (overlaps compute below)
            pa0 = loadA(lrow, kn);
            pa1 = loadA(lrow + 64, kn);
            if (MODE == 0) { pb0 = loadBtr(lrow, kn);  pb1 = loadBtr(lrow + 64, kn); }
            else           { pb0 = loadBdir(brow, kn); pb1 = loadBdir(brow + 8, kn); }
        }

#pragma unroll
        for (int k = 0; k < BK; k++) {
            float4 a0 = *(const float4*)&As[k][m0];
            float4 a1 = *(const float4*)&As[k][m0 + 4];
            float4 b0 = *(const float4*)&Bs[k][n0];
            float4 b1 = *(const float4*)&Bs[k][n0 + 4];
            float av[8] = {a0.x, a0.y, a0.z, a0.w, a1.x, a1.y, a1.z, a1.w};
            float bv[8] = {b0.x, b0.y, b0.z, b0.w, b1.x, b1.y, b1.z, b1.w};
#pragma unroll
            for (int i = 0; i < 8; i++)
#pragma unroll
                for (int j = 0; j < 8; j++)
                    acc[i][j] = fmaf(av[i], bv[j], acc[i][j]);
        }
        __syncthreads();
    }

    float bb[8];
    if (MODE == 2) {
#pragma unroll
        for (int j = 0; j < 8; j++) bb[j] = bias[bn + n0 + j];
    }

#pragma unroll
    for (int i = 0; i < 8; i++) {
        float4 o0, o1;
        if (MODE == 0) {
            o0 = make_float4(acc[i][0] * SCALE, acc[i][1] * SCALE,
                             acc[i][2] * SCALE, acc[i][3] * SCALE);
            o1 = make_float4(acc[i][4] * SCALE, acc[i][5] * SCALE,
                             acc[i][6] * SCALE, acc[i][7] * SCALE);
        } else if (MODE == 1) {
            o0 = make_float4(acc[i][0], acc[i][1], acc[i][2], acc[i][3]);
            o1 = make_float4(acc[i][4], acc[i][5], acc[i][6], acc[i][7]);
        } else {
            o0 = make_float4(acc[i][0] + bb[0], acc[i][1] + bb[1],
                             acc[i][2] + bb[2], acc[i][3] + bb[3]);
            o1 = make_float4(acc[i][4] + bb[4], acc[i][5] + bb[5],
                             acc[i][6] + bb[6], acc[i][7] + bb[7]);
        }
        float* cp = C + (size_t)(bm + m0 + i) * ldc + bn + n0;
        *(float4*)cp       = o0;
        *(float4*)(cp + 4) = o1;
    }
}

// ---------------------------------------------------------------------------
// Block reductions (256 threads)
// ---------------------------------------------------------------------------
__device__ __forceinline__ float block_reduce_sum(float v) {
    __shared__ float red[8];
#pragma unroll
    for (int o = 16; o > 0; o >>= 1) v += __shfl_xor_sync(0xffffffffu, v, o);
    if ((threadIdx.x & 31) == 0) red[threadIdx.x >> 5] = v;
    __syncthreads();
    float t = red[0];
#pragma unroll
    for (int i = 1; i < 8; i++) t += red[i];
    __syncthreads();
    return t;
}

__device__ __forceinline__ float block_reduce_max(float v) {
    __shared__ float red[8];
#pragma unroll
    for (int o = 16; o > 0; o >>= 1) v = fmaxf(v, __shfl_xor_sync(0xffffffffu, v, o));
    if ((threadIdx.x & 31) == 0) red[threadIdx.x >> 5] = v;
    __syncthreads();
    float t = red[0];
#pragma unroll
    for (int i = 1; i < 8; i++) t = fmaxf(t, red[i]);
    __syncthreads();
    return t;
}

// ---------------------------------------------------------------------------
// Masked softmax over rows of g_probs (in place). One block per [b,s] row.
// ---------------------------------------------------------------------------
__global__ __launch_bounds__(256)
void k_softmax(const float* __restrict__ masks) {
    const size_t row = blockIdx.x;
    float* p        = g_probs + row * (size_t)S_;
    const float* mk = masks   + row * (size_t)S_;
    const int tid = threadIdx.x;

    float4 s0 = ((const float4*)p)[2 * tid];
    float4 s1 = ((const float4*)p)[2 * tid + 1];
    float4 m0 = ((const float4*)mk)[2 * tid];
    float4 m1 = ((const float4*)mk)[2 * tid + 1];

    float v[8] = {
        s0.x * m0.x - MASKC * (1.0f - m0.x), s0.y * m0.y - MASKC * (1.0f - m0.y),
        s0.z * m0.z - MASKC * (1.0f - m0.z), s0.w * m0.w - MASKC * (1.0f - m0.w),
        s1.x * m1.x - MASKC * (1.0f - m1.x), s1.y * m1.y - MASKC * (1.0f - m1.y),
        s1.z * m1.z - MASKC * (1.0f - m1.z), s1.w * m1.w - MASKC * (1.0f - m1.w)};

    float mx = v[0];
#pragma unroll
    for (int i = 1; i < 8; i++) mx = fmaxf(mx, v[i]);
    mx = block_reduce_max(mx);

    float sum = 0.0f;
#pragma unroll
    for (int i = 0; i < 8; i++) { v[i] = __expf(v[i] - mx); sum += v[i]; }
    sum = block_reduce_sum(sum);
    const float inv = 1.0f / sum;   // >= 1 always (max term contributes exp(0)=1)

    ((float4*)p)[2 * tid]     = make_float4(v[0] * inv, v[1] * inv, v[2] * inv, v[3] * inv);
    ((float4*)p)[2 * tid + 1] = make_float4(v[4] * inv, v[5] * inv, v[6] * inv, v[7] * inv);
}

// ---------------------------------------------------------------------------
// LayerNorm over H. One block per [b,s] row, 4 elems/thread.
// ---------------------------------------------------------------------------
__global__ __launch_bounds__(256)
void k_ln(const float* __restrict__ gamma, const float* __restrict__ beta,
          float* __restrict__ out) {
    const size_t row = blockIdx.x;
    const float* x = g_match + row * (size_t)H_;
    const int tid = threadIdx.x;

    float4 xv = ((const float4*)x)[tid];
    float s = (xv.x + xv.y) + (xv.z + xv.w);
    float mu = block_reduce_sum(s) * (1.0f / H_);

    float d0 = xv.x - mu, d1 = xv.y - mu, d2 = xv.z - mu, d3 = xv.w - mu;
    float sq = d0 * d0 + d1 * d1 + d2 * d2 + d3 * d3;
    float var = block_reduce_sum(sq) * (1.0f / H_);
    float rstd = rsqrtf(var + LN_EPS);

    float4 g  = ((const float4*)gamma)[tid];
    float4 bt = ((const float4*)beta)[tid];
    float4 o = make_float4(d0 * rstd * g.x + bt.x, d1 * rstd * g.y + bt.y,
                           d2 * rstd * g.z + bt.z, d3 * rstd * g.w + bt.w);
    ((float4*)(out + row * (size_t)H_))[tid] = o;
}

// ---------------------------------------------------------------------------
// Launch (graph-capturable: kernel launches only, no allocs/syncs).
// Input order per metadata: inputs, masks, w_match, b_match, ln_gamma, ln_beta.
// ---------------------------------------------------------------------------
extern "C" void kernel_launch(void* const* d_in, const int* in_sizes, int n_in,
                              void* d_out, int out_size) {
    const float* inputs = (const float*)d_in[0];
    const float* masks  = (const float*)d_in[1];
    const float* wmat   = (const float*)d_in[2];
    const float* bmat   = (const float*)d_in[3];
    const float* gamma  = (const float*)d_in[4];
    const float* beta   = (const float*)d_in[5];
    float* out = (float*)d_out;
    (void)in_sizes; (void)n_in; (void)out_size;

    dim3 gScores(S_ / BN, S_ / BM, B_);   // (16,16,8)
    dim3 gHN(H_ / BN, S_ / BM, B_);       // (8,16,8)

    k_gemm<0><<<gScores, 256>>>(inputs, nullptr, nullptr);
    k_softmax<<<B_ * S_, 256>>>(masks);
    k_gemm<1><<<gHN, 256>>>(inputs, nullptr, nullptr);
    k_gemm<2><<<gHN, 256>>>(inputs, wmat, bmat);
    k_ln<<<B_ * S_, 256>>>(gamma, beta, out);
}

// round 16
// speedup vs baseline: 1.0008x; 1.0008x over previous
#include <cuda_runtime.h>

// ---------------------------------------------------------------------------
// MatchingLayer: B=8, S=2048, H=1024
//   scores  = (X @ X^T) / sqrt(H)                      [B,S,S]
//   probs   = softmax(scores*mask - 1e9*(1-mask))      [B,S,S]
//   context = probs @ X                                 [B,S,H]
//   match   = [X | context] @ W(2H,H) + b               [B,S,H]
//   out     = LayerNorm(match) * gamma + beta           [B,S,H]
// ---------------------------------------------------------------------------

namespace {
constexpr int B_ = 8;
constexpr int S_ = 2048;
constexpr int H_ = 1024;
constexpr int BM = 128, BN = 128, BK = 16;
constexpr float SCALE = 0.03125f;      // 1/sqrt(1024)
constexpr float MASKC = 1.0e9f;        // MASK_LOGIT_CONST
constexpr float LN_EPS = 1e-12f;
}

// Scratch (module-static device memory; no runtime allocation).
__device__ __align__(16) float g_probs[(size_t)B_ * S_ * S_];   // 134 MB, reused scores->probs
__device__ __align__(16) float g_ctx  [(size_t)B_ * S_ * H_];   // 67 MB
__device__ __align__(16) float g_match[(size_t)B_ * S_ * H_];   // 67 MB

// ---------------------------------------------------------------------------
// Tiled SGEMM, 128x128x16 tile, 256 threads, 8x8 register microtile.
// MODE 0: C = Xb @ Xb^T * SCALE        (M=S, N=S, K=H)   -> g_probs
// MODE 1: C = Pb @ Xb                  (M=S, N=H, K=S)   -> g_ctx
// MODE 2: C = [Xb|Ctx] @ W + bias      (M=S, N=H, K=2H)  -> g_match
// ---------------------------------------------------------------------------
template <int MODE>
__global__ __launch_bounds__(256, 2)
void k_gemm(const float* __restrict__ X,
            const float* __restrict__ W,
            const float* __restrict__ bias) {
    constexpr int KDIM = (MODE == 0) ? H_ : (MODE == 1 ? S_ : 2 * H_);
    const int b  = blockIdx.z;
    const int bm = blockIdx.y * BM;
    const int bn = blockIdx.x * BN;

    const float* Xb  = X + (size_t)b * S_ * H_;
    const float* Pb  = g_probs + (size_t)b * S_ * S_;
    const float* Ctx = g_ctx   + (size_t)b * S_ * H_;
    float* C = (MODE == 0) ? g_probs + (size_t)b * S_ * S_
             : (MODE == 1) ? g_ctx   + (size_t)b * S_ * H_
                           : g_match + (size_t)b * S_ * H_;
    const int ldc = (MODE == 0) ? S_ : H_;

    __shared__ __align__(16) float As[BK][BM + 4];
    __shared__ __align__(16) float Bs[BK][BN + 4];

    const int tid  = threadIdx.x;
    const int lrow = tid >> 2;           // 0..63 (transposed-loader row)
    const int lk   = (tid & 3) * 4;      // 0,4,8,12
    const int brow = tid >> 5;           // 0..7  (direct B loader row)
    const int bcol = (tid & 31) * 4;     // 0..124
    const int tx = tid & 15, ty = tid >> 4;
    const int m0 = ty * 8, n0 = tx * 8;

    float acc[8][8];
#pragma unroll
    for (int i = 0; i < 8; i++)
#pragma unroll
        for (int j = 0; j < 8; j++) acc[i][j] = 0.0f;

    // A is always loaded "transposed" (As[k][m]) from a row-major [M,K] source.
    auto loadA = [&](int row, int k0) -> float4 {
        if (MODE == 0)
            return *(const float4*)(Xb + (size_t)(bm + row) * H_ + k0 + lk);
        else if (MODE == 1)
            return *(const float4*)(Pb + (size_t)(bm + row) * S_ + k0 + lk);
        else {
            int kk = k0 + lk;   // whole BK-tile is on one side of H (H % BK == 0)
            const float* src = (kk < H_)
                ? (Xb  + (size_t)(bm + row) * H_ + kk)
                : (Ctx + (size_t)(bm + row) * H_ + (kk - H_));
            return *(const float4*)src;
        }
    };
    // MODE 0: B tile is also transposed rows of Xb (for X @ X^T).
    auto loadBtr = [&](int row, int k0) -> float4 {
        return *(const float4*)(Xb + (size_t)(bn + row) * H_ + k0 + lk);
    };
    // MODE 1/2: B is row-major [K,N]; direct load Bs[k][n].
    auto loadBdir = [&](int r, int k0) -> float4 {
        const float* base = (MODE == 1) ? Xb : W;
        return *(const float4*)(base + (size_t)(k0 + r) * H_ + bn + bcol);
    };

    float4 pa0 = loadA(lrow, 0);
    float4 pa1 = loadA(lrow + 64, 0);
    float4 pb0, pb1;
    if (MODE == 0) { pb0 = loadBtr(lrow, 0);  pb1 = loadBtr(lrow + 64, 0); }
    else           { pb0 = loadBdir(brow, 0); pb1 = loadBdir(brow + 8, 0); }

    for (int k0 = 0; k0 < KDIM; k0 += BK) {
        // commit prefetched tile to smem
        As[lk + 0][lrow] = pa0.x; As[lk + 1][lrow] = pa0.y;
        As[lk + 2][lrow] = pa0.z; As[lk + 3][lrow] = pa0.w;
        As[lk + 0][lrow + 64] = pa1.x; As[lk + 1][lrow + 64] = pa1.y;
        As[lk + 2][lrow + 64] = pa1.z; As[lk + 3][lrow + 64] = pa1.w;
        if (MODE == 0) {
            Bs[lk + 0][lrow] = pb0.x; Bs[lk + 1][lrow] = pb0.y;
            Bs[lk + 2][lrow] = pb0.z; Bs[lk + 3][lrow] = pb0.w;
            Bs[lk + 0][lrow + 64] = pb1.x; Bs[lk + 1][lrow + 64] = pb1.y;
            Bs[lk + 2][lrow + 64] = pb1.z; Bs[lk + 3][lrow + 64] = pb1.w;
        } else {
            *(float4*)&Bs[brow][bcol]     = pb0;
            *(float4*)&Bs[brow + 8][bcol] = pb1;
        }
        __syncthreads();

        const int kn = k0 + BK;
        if (kn < KDIM) {  // prefetch next tile (overlaps compute below)
            pa0 = loadA(lrow, kn);
            pa1 = loadA(lrow + 64, kn);
            if (MODE == 0) { pb0 = loadBtr(lrow, kn);  pb1 = loadBtr(lrow + 64, kn); }
            else           { pb0 = loadBdir(brow, kn); pb1 = loadBdir(brow + 8, kn); }
        }

#pragma unroll
        for (int k = 0; k < BK; k++) {
            float4 a0 = *(const float4*)&As[k][m0];
            float4 a1 = *(const float4*)&As[k][m0 + 4];
            float4 b0 = *(const float4*)&Bs[k][n0];
            float4 b1 = *(const float4*)&Bs[k][n0 + 4];
            float av[8] = {a0.x, a0.y, a0.z, a0.w, a1.x, a1.y, a1.z, a1.w};
            float bv[8] = {b0.x, b0.y, b0.z, b0.w, b1.x, b1.y, b1.z, b1.w};
#pragma unroll
            for (int i = 0; i < 8; i++)
#pragma unroll
                for (int j = 0; j < 8; j++)
                    acc[i][j] = fmaf(av[i], bv[j], acc[i][j]);
        }
        __syncthreads();
    }

    float bb[8];
    if (MODE == 2) {
#pragma unroll
        for (int j = 0; j < 8; j++) bb[j] = bias[bn + n0 + j];
    }

#pragma unroll
    for (int i = 0; i < 8; i++) {
        float4 o0, o1;
        if (MODE == 0) {
            o0 = make_float4(acc[i][0] * SCALE, acc[i][1] * SCALE,
                             acc[i][2] * SCALE, acc[i][3] * SCALE);
            o1 = make_float4(acc[i][4] * SCALE, acc[i][5] * SCALE,
                             acc[i][6] * SCALE, acc[i][7] * SCALE);
        } else if (MODE == 1) {
            o0 = make_float4(acc[i][0], acc[i][1], acc[i][2], acc[i][3]);
            o1 = make_float4(acc[i][4], acc[i][5], acc[i][6], acc[i][7]);
        } else {
            o0 = make_float4(acc[i][0] + bb[0], acc[i][1] + bb[1],
                             acc[i][2] + bb[2], acc[i][3] + bb[3]);
            o1 = make_float4(acc[i][4] + bb[4], acc[i][5] + bb[5],
                             acc[i][6] + bb[6], acc[i][7] + bb[7]);
        }
        float* cp = C + (size_t)(bm + m0 + i) * ldc + bn + n0;
        *(float4*)cp       = o0;
        *(float4*)(cp + 4) = o1;
    }
}

// ---------------------------------------------------------------------------
// Block reductions (256 threads)
// ---------------------------------------------------------------------------
__device__ __forceinline__ float block_reduce_sum(float v) {
    __shared__ float red[8];
#pragma unroll
    for (int o = 16; o > 0; o >>= 1) v += __shfl_xor_sync(0xffffffffu, v, o);
    if ((threadIdx.x & 31) == 0) red[threadIdx.x >> 5] = v;
    __syncthreads();
    float t = red[0];
#pragma unroll
    for (int i = 1; i < 8; i++) t += red[i];
    __syncthreads();
    return t;
}

__device__ __forceinline__ float block_reduce_max(float v) {
    __shared__ float red[8];
#pragma unroll
    for (int o = 16; o > 0; o >>= 1) v = fmaxf(v, __shfl_xor_sync(0xffffffffu, v, o));
    if ((threadIdx.x & 31) == 0) red[threadIdx.x >> 5] = v;
    __syncthreads();
    float t = red[0];
#pragma unroll
    for (int i = 1; i < 8; i++) t = fmaxf(t, red[i]);
    __syncthreads();
    return t;
}

// ---------------------------------------------------------------------------
// Masked softmax over rows of g_probs (in place). One block per [b,s] row.
// ---------------------------------------------------------------------------
__global__ __launch_bounds__(256)
void k_softmax(const float* __restrict__ masks) {
    const size_t row = blockIdx.x;
    float* p        = g_probs + row * (size_t)S_;
    const float* mk = masks   + row * (size_t)S_;
    const int tid = threadIdx.x;

    float4 s0 = ((const float4*)p)[2 * tid];
    float4 s1 = ((const float4*)p)[2 * tid + 1];
    float4 m0 = ((const float4*)mk)[2 * tid];
    float4 m1 = ((const float4*)mk)[2 * tid + 1];

    float v[8] = {
        s0.x * m0.x - MASKC * (1.0f - m0.x), s0.y * m0.y - MASKC * (1.0f - m0.y),
        s0.z * m0.z - MASKC * (1.0f - m0.z), s0.w * m0.w - MASKC * (1.0f - m0.w),
        s1.x * m1.x - MASKC * (1.0f - m1.x), s1.y * m1.y - MASKC * (1.0f - m1.y),
        s1.z * m1.z - MASKC * (1.0f - m1.z), s1.w * m1.w - MASKC * (1.0f - m1.w)};

    float mx = v[0];
#pragma unroll
    for (int i = 1; i < 8; i++) mx = fmaxf(mx, v[i]);
    mx = block_reduce_max(mx);

    float sum = 0.0f;
#pragma unroll
    for (int i = 0; i < 8; i++) { v[i] = __expf(v[i] - mx); sum += v[i]; }
    sum = block_reduce_sum(sum);
    const float inv = 1.0f / sum;   // >= 1 always (max term contributes exp(0)=1)

    ((float4*)p)[2 * tid]     = make_float4(v[0] * inv, v[1] * inv, v[2] * inv, v[3] * inv);
    ((float4*)p)[2 * tid + 1] = make_float4(v[4] * inv, v[5] * inv, v[6] * inv, v[7] * inv);
}

// ---------------------------------------------------------------------------
// LayerNorm over H. One block per [b,s] row, 4 elems/thread.
// ---------------------------------------------------------------------------
__global__ __launch_bounds__(256)
void k_ln(const float* __restrict__ gamma, const float* __restrict__ beta,
          float* __restrict__ out) {
    const size_t row = blockIdx.x;
    const float* x = g_match + row * (size_t)H_;
    const int tid = threadIdx.x;

    float4 xv = ((const float4*)x)[tid];
    float s = (xv.x + xv.y) + (xv.z + xv.w);
    float mu = block_reduce_sum(s) * (1.0f / H_);

    float d0 = xv.x - mu, d1 = xv.y - mu, d2 = xv.z - mu, d3 = xv.w - mu;
    float sq = d0 * d0 + d1 * d1 + d2 * d2 + d3 * d3;
    float var = block_reduce_sum(sq) * (1.0f / H_);
    float rstd = rsqrtf(var + LN_EPS);

    float4 g  = ((const float4*)gamma)[tid];
    float4 bt = ((const float4*)beta)[tid];
    float4 o = make_float4(d0 * rstd * g.x + bt.x, d1 * rstd * g.y + bt.y,
                           d2 * rstd * g.z + bt.z, d3 * rstd * g.w + bt.w);
    ((float4*)(out + row * (size_t)H_))[tid] = o;
}

// ---------------------------------------------------------------------------
// Launch (graph-capturable: kernel launches only, no allocs/syncs).
// Input order per metadata: inputs, masks, w_match, b_match, ln_gamma, ln_beta.
// ---------------------------------------------------------------------------
extern "C" void kernel_launch(void* const* d_in, const int* in_sizes, int n_in,
                              void* d_out, int out_size) {
    const float* inputs = (const float*)d_in[0];
    const float* masks  = (const float*)d_in[1];
    const float* wmat   = (const float*)d_in[2];
    const float* bmat   = (const float*)d_in[3];
    const float* gamma  = (const float*)d_in[4];
    const float* beta   = (const float*)d_in[5];
    float* out = (float*)d_out;
    (void)in_sizes; (void)n_in; (void)out_size;

    dim3 gScores(S_ / BN, S_ / BM, B_);   // (16,16,8)
    dim3 gHN(H_ / BN, S_ / BM, B_);       // (8,16,8)

    k_gemm<0><<<gScores, 256>>>(inputs, nullptr, nullptr);
    k_softmax<<<B_ * S_, 256>>>(masks);
    k_gemm<1><<<gHN, 256>>>(inputs, nullptr, nullptr);
    k_gemm<2><<<gHN, 256>>>(inputs, wmat, bmat);
    k_ln<<<B_ * S_, 256>>>(gamma, beta, out);
}